// round 1
// baseline (speedup 1.0000x reference)
#include <cuda_runtime.h>
#include <math.h>

#define CCH   128
#define HW    262144          // 512*512
#define NB    256

// 128MB key scratch + loss accumulator (static __device__ — allocation-free)
__device__ unsigned int g_keys[(size_t)CCH * HW];
__device__ double g_loss;

__device__ __forceinline__ unsigned int fkey(float x) {
    unsigned int u = __float_as_uint(x);
    return (u & 0x80000000u) ? ~u : (u | 0x80000000u);
}
__device__ __forceinline__ float dkey(unsigned int k) {
    return __uint_as_float((k & 0x80000000u) ? (k & 0x7fffffffu) : ~k);
}

__global__ void init_kernel() { g_loss = 0.0; }

__global__ void finish_kernel(float* out) {
    out[0] = (float)(g_loss * (0.01 / ((double)CCH * (double)HW)));
}

// shared memory layout (u32 units):
//  HIST      [0,      32768)   packed u16x2 histogram (64K bins / 256x256 refinement)
//  cutP      [32768,  33024)
//  cutR      [33024,  33280)
//  cutS      [33280,  33536)
//  uniq      [33536,  33792)   (also cdf float temp)
//  sgrp      [33792,  34049)
//  th        [34049,  34305)   (also K_j temp)
//  chist     [34305,  34561)
//  red       [34561,  34633)   reduction scratch + scalars
#define SMEM_WORDS 34633
#define SMEM_BYTES (SMEM_WORDS * 4)

extern __shared__ unsigned int smem[];

__global__ void __launch_bounds__(1024, 1)
main_kernel(const float* __restrict__ input, const float* __restrict__ mask,
            const float* __restrict__ thist, const float* __restrict__ tmin_,
            const float* __restrict__ tmax_, float* __restrict__ out)
{
    unsigned int* HIST  = smem;
    unsigned int* cutP  = smem + 32768;
    unsigned int* cutR  = cutP + 256;
    unsigned int* cutS  = cutR + 256;
    unsigned int* uniq  = cutS + 256;
    unsigned int* sgrp  = uniq + 256;   // 257 entries
    unsigned int* th    = sgrp + 257;
    unsigned int* chist = th + 256;
    unsigned int* red   = chist + 256;  // 72 entries

    const int c   = blockIdx.x;
    const int tid = threadIdx.x;
    const int NT  = 1024;

    // zero histograms
    for (int i = tid; i < 32768; i += NT) HIST[i] = 0;
    if (tid < 256) chist[tid] = 0;
    __syncthreads();

    // ---------------- Phase 0: keys + min/max + 16-bit histogram ----------------
    {
        const float4* in4 = (const float4*)(input + (size_t)c * HW);
        const float4* mk4 = (const float4*)mask;
        uint4* key4 = (uint4*)(g_keys + (size_t)c * HW);
        unsigned int kmin = 0xffffffffu, kmax = 0u;

        for (int i = tid; i < HW / 4; i += NT) {
            float4 a = in4[i];
            float4 m = mk4[i];
            uint4 k;
            k.x = fkey(a.x * m.x);
            k.y = fkey(a.y * m.y);
            k.z = fkey(a.z * m.z);
            k.w = fkey(a.w * m.w);
            key4[i] = k;
            unsigned int kk;
            kk = k.x; kmin = min(kmin, kk); kmax = max(kmax, kk);
            { unsigned b = kk >> 16; atomicAdd(&HIST[b >> 1], (b & 1) ? 65536u : 1u); }
            kk = k.y; kmin = min(kmin, kk); kmax = max(kmax, kk);
            { unsigned b = kk >> 16; atomicAdd(&HIST[b >> 1], (b & 1) ? 65536u : 1u); }
            kk = k.z; kmin = min(kmin, kk); kmax = max(kmax, kk);
            { unsigned b = kk >> 16; atomicAdd(&HIST[b >> 1], (b & 1) ? 65536u : 1u); }
            kk = k.w; kmin = min(kmin, kk); kmax = max(kmax, kk);
            { unsigned b = kk >> 16; atomicAdd(&HIST[b >> 1], (b & 1) ? 65536u : 1u); }
        }
        // block reduce min/max
        #pragma unroll
        for (int off = 16; off; off >>= 1) {
            kmin = min(kmin, __shfl_down_sync(0xffffffffu, kmin, off));
            kmax = max(kmax, __shfl_down_sync(0xffffffffu, kmax, off));
        }
        if ((tid & 31) == 0) { red[tid >> 5] = kmin; red[32 + (tid >> 5)] = kmax; }
    }
    __syncthreads();
    if (tid == 0) {
        unsigned mn = red[0], mx = red[32];
        for (int w = 1; w < 32; w++) { mn = min(mn, red[w]); mx = max(mx, red[32 + w]); }
        red[64] = mn; red[65] = mx;
    }

    // ---------------- Phase 1: target CDF -> K_j (thread 0, sequential f32) -----
    if (tid == 0) {
        float* cdf = (float*)uniq;
        float s = 0.0f;
        for (int j = 0; j < 256; j++) { s += thist[c * 256 + j]; cdf[j] = s; }
        float tot = s;
        for (int j = 0; j < 256; j++) {
            float t = (cdf[j] / tot) * 262144.0f;
            float f = floorf(t);
            if (f < 0.0f) f = 0.0f;
            if (f > 262144.0f) f = 262144.0f;
            th[j] = (unsigned)f;      // K_j stored temporarily in th[]
        }
    }
    __syncthreads();

    // ---------------- Phase 2: locate cut bins in 16-bit histogram --------------
    if (tid < 256) {
        unsigned s = 0;
        for (int w = 0; w < 128; w++) {
            unsigned v = HIST[tid * 128 + w];
            s += (v & 0xffffu) + (v >> 16);
        }
        sgrp[tid] = s;
    }
    __syncthreads();
    if (tid == 0) {
        unsigned acc = 0;
        for (int g = 0; g < 256; g++) { unsigned t = sgrp[g]; sgrp[g] = acc; acc += t; }
        sgrp[256] = acc;
    }
    __syncthreads();
    if (tid < 256) {
        unsigned k = th[tid];   // K_j
        if (k == 0) {
            cutP[tid] = 0xffffffffu; cutR[tid] = 0;
        } else {
            int lo = 0, hi = 255;                   // largest g with sgrp[g] < k
            while (lo < hi) { int mid = (lo + hi + 1) >> 1; if (sgrp[mid] < k) lo = mid; else hi = mid - 1; }
            unsigned acc = sgrp[lo];
            int bin = lo * 256;
            for (;; bin++) {
                unsigned w = HIST[bin >> 1];
                unsigned cnt = (bin & 1) ? (w >> 16) : (w & 0xffffu);
                if (acc + cnt >= k) break;
                acc += cnt;
            }
            cutP[tid] = (unsigned)bin;
            cutR[tid] = k - acc;
        }
    }
    __syncthreads();

    // ---------------- Phase 3: two 8-bit refinement rounds -----------------------
    for (int r = 0; r < 2; r++) {
        const int shiftP = (r == 0) ? 16 : 8;
        const int shiftS = (r == 0) ? 8 : 0;

        if (tid == 0) {          // unique (sorted: order stats monotone) prefix list
            int n = 0; unsigned prev = 0xffffffffu;
            for (int j = 0; j < 256; j++) {
                unsigned p = cutP[j];
                if (p != 0xffffffffu) {
                    if (n == 0 || p != prev) { uniq[n] = p; prev = p; n++; }
                    cutS[j] = (unsigned)(n - 1);
                }
            }
            red[66] = (unsigned)n;
        }
        __syncthreads();
        const int nU = (int)red[66];
        for (int i = tid; i < 32768; i += NT) HIST[i] = 0;
        __syncthreads();

        if (nU > 0) {
            const uint4* k4 = (const uint4*)(g_keys + (size_t)c * HW);
            for (int i = tid; i < HW / 4; i += NT) {
                uint4 kk = k4[i];
                #pragma unroll
                for (int e = 0; e < 4; e++) {
                    unsigned key = (e == 0) ? kk.x : (e == 1) ? kk.y : (e == 2) ? kk.z : kk.w;
                    unsigned p = key >> shiftP;
                    int lo = 0, hi = nU;
                    while (lo < hi) { int mid = (lo + hi) >> 1; if (uniq[mid] < p) lo = mid + 1; else hi = mid; }
                    if (lo < nU && uniq[lo] == p) {
                        unsigned sub = (key >> shiftS) & 0xffu;
                        unsigned idx = (unsigned)lo * 256u + sub;
                        atomicAdd(&HIST[idx >> 1], (idx & 1) ? 65536u : 1u);
                    }
                }
            }
        }
        __syncthreads();

        if (tid < 256 && cutP[tid] != 0xffffffffu) {
            unsigned s = cutS[tid], k = cutR[tid], acc = 0;
            unsigned base = s * 256u;
            int sub = 0;
            for (;; sub++) {
                unsigned idx = base + (unsigned)sub;
                unsigned w = HIST[idx >> 1];
                unsigned cnt = (idx & 1) ? (w >> 16) : (w & 0xffffu);
                if (acc + cnt >= k) break;
                acc += cnt;
            }
            cutP[tid] = (cutP[tid] << 8) | (unsigned)sub;
            cutR[tid] = k - acc;
        }
        __syncthreads();
    }

    // final thresholds (sorted nondecreasing: K_j nondecreasing)
    if (tid < 256) th[tid] = (cutP[tid] == 0xffffffffu) ? 0u : cutP[tid];
    __syncthreads();

    // ---------------- Phase 4: cur_hist + matched + loss -------------------------
    {
        const float mn = dkey(red[64]);
        const float mx = dkey(red[65]);
        const float dd = fmaxf(mx - mn, 1e-8f);
        const float tmn = tmin_[c];
        const float scl = tmax_[c] - tmn;
        float acc = 0.0f;

        const uint4* k4 = (const uint4*)(g_keys + (size_t)c * HW);
        for (int i = tid; i < HW / 4; i += NT) {
            uint4 kk = k4[i];
            #pragma unroll
            for (int e = 0; e < 4; e++) {
                unsigned key = (e == 0) ? kk.x : (e == 1) ? kk.y : (e == 2) ? kk.z : kk.w;
                float v = dkey(key);
                // current histogram (exact counts)
                float u = (v - mn) / dd;
                int b = (int)(u * 255.0f);
                b = min(max(b, 0), 255);
                atomicAdd(&chist[b], 1u);
                // matched bin = #{th < key}
                int lo = 0, hi = 256;
                while (lo < hi) { int mid = (lo + hi) >> 1; if (th[mid] < key) lo = mid + 1; else hi = mid; }
                int bm = min(lo, 255);
                float tgt = ((float)bm / 255.0f) * scl + tmn;
                float df = v - tgt;
                acc += df * df;
            }
        }
        // block reduce loss partial
        #pragma unroll
        for (int off = 16; off; off >>= 1)
            acc += __shfl_down_sync(0xffffffffu, acc, off);
        __syncthreads();
        if ((tid & 31) == 0) ((float*)red)[tid >> 5] = acc;
        __syncthreads();
        if (tid == 0) {
            float s = 0.0f;
            for (int w = 0; w < 32; w++) s += ((float*)red)[w];
            atomicAdd(&g_loss, (double)s);
        }

        // outputs: [0]=loss, [1..32769)=cur_hist, then cur_min, cur_max
        if (tid < 256) out[1 + c * 256 + tid] = (float)chist[tid];
        if (tid == 0) {
            out[1 + 32768 + c]       = mn;
            out[1 + 32768 + 128 + c] = mx;
        }
    }
}

extern "C" void kernel_launch(void* const* d_in, const int* in_sizes, int n_in,
                              void* d_out, int out_size)
{
    const float* input = (const float*)d_in[0];
    const float* mask  = (const float*)d_in[1];
    const float* thist = (const float*)d_in[2];
    const float* tmn   = (const float*)d_in[3];
    const float* tmx   = (const float*)d_in[4];
    float* out = (float*)d_out;

    cudaFuncSetAttribute(main_kernel, cudaFuncAttributeMaxDynamicSharedMemorySize, SMEM_BYTES);

    init_kernel<<<1, 1>>>();
    main_kernel<<<CCH, 1024, SMEM_BYTES>>>(input, mask, thist, tmn, tmx, out);
    finish_kernel<<<1, 1>>>(out);
}